// round 14
// baseline (speedup 1.0000x reference)
#include <cuda_runtime.h>
#include <cstdint>

#define NTOK  343
#define PSTR  352          // padded j-extent (16-divisible) for PV
#define NHEAD 8
#define CDIM  256
#define HD    32
#define BWIN  256
#define NWND  64
#define NN    (NTOK * NTOK)   // 117649
#define QSCALE 0.17677669529663687f   // 32^-0.5
#define LOG2E  1.4426950408889634f

// ---------------- scratch (device globals: no allocation allowed) ----------------
__device__ float g_q[(size_t)BWIN * NHEAD * NTOK * HD];   // scaled q, (Bw,H,n,hd)
__device__ float g_k[(size_t)BWIN * NHEAD * NTOK * HD];
__device__ float g_v[(size_t)BWIN * NHEAD * NTOK * HD];
__device__ float g_o[(size_t)BWIN * NTOK * CDIM];         // attention out, (Bw,n,C)
__device__ float g_bias[(size_t)NHEAD * NN];              // gathered rpb bias (H,n,n)

// ---------------- packed fp32x2 helpers ----------------
__device__ __forceinline__ void fma2(unsigned long long& acc,
                                     const unsigned long long a,
                                     const unsigned long long b) {
    asm("fma.rn.f32x2 %0, %1, %2, %0;" : "+l"(acc) : "l"(a), "l"(b));
}
__device__ __forceinline__ float2 unpack2(const unsigned long long x) {
    float2 r;
    asm("mov.b64 {%0, %1}, %2;" : "=f"(r.x), "=f"(r.y) : "l"(x));
    return r;
}

// =================================================================================
// Kernel 0: gather relative-position bias: g_bias[h][p] = rpb[rel_idx[p]*8 + h]
// =================================================================================
__global__ __launch_bounds__(256) void bias_gather_kernel(
    const float* __restrict__ rpb,
    const int*   __restrict__ rel_idx)
{
    const int p = blockIdx.x * 256 + threadIdx.x;
    if (p >= NN) return;
    const int idx = rel_idx[p];
    float4 r0 = *(const float4*)(rpb + (size_t)idx * 8);
    float4 r1 = *(const float4*)(rpb + (size_t)idx * 8 + 4);
    g_bias[0 * (size_t)NN + p] = r0.x;
    g_bias[1 * (size_t)NN + p] = r0.y;
    g_bias[2 * (size_t)NN + p] = r0.z;
    g_bias[3 * (size_t)NN + p] = r0.w;
    g_bias[4 * (size_t)NN + p] = r1.x;
    g_bias[5 * (size_t)NN + p] = r1.y;
    g_bias[6 * (size_t)NN + p] = r1.z;
    g_bias[7 * (size_t)NN + p] = r1.w;
}

// =================================================================================
// Shared GEMM macros (BM=128, BN=128, BK=8 double-buffered, 256 threads, 8x8)
// =================================================================================
#define QKV_STAGE(BUF, KK)                                                  \
    {                                                                       \
        float a[8], b[8];                                                   \
        *(float4*)(a)     = *(const float4*)&As[BUF][KK][ty * 8];           \
        *(float4*)(a + 4) = *(const float4*)&As[BUF][KK][ty * 8 + 4];       \
        *(float4*)(b)     = *(const float4*)&Bs[BUF][KK][tx * 8];           \
        *(float4*)(b + 4) = *(const float4*)&Bs[BUF][KK][tx * 8 + 4];       \
        _Pragma("unroll")                                                   \
        for (int u = 0; u < 8; u++)                                         \
            _Pragma("unroll")                                               \
            for (int v = 0; v < 8; v++) acc[u][v] += a[u] * b[v];           \
    }
#define QKV_COMPUTE(BUF)                                                    \
    { _Pragma("unroll") for (int kk = 0; kk < 8; kk++) QKV_STAGE(BUF, kk) }
#define QKV_STORE(BUF, AV, BV)                                              \
    {                                                                       \
        As[BUF][akg + 0][arow] = (AV).x;                                    \
        As[BUF][akg + 1][arow] = (AV).y;                                    \
        As[BUF][akg + 2][arow] = (AV).z;                                    \
        As[BUF][akg + 3][arow] = (AV).w;                                    \
        *(float4*)&Bs[BUF][brow][bc] = (BV);                                \
    }

// =================================================================================
// Kernel 1: QKV = x @ qkv_w + qkv_b, scatter to g_q (scaled), g_k, g_v
// =================================================================================
__global__ __launch_bounds__(256) void qkv_gemm_kernel(
    const float* __restrict__ x,
    const float* __restrict__ w,
    const float* __restrict__ bias)
{
    __shared__ float As[2][8][132];
    __shared__ float Bs[2][8][132];

    const int tid = threadIdx.x;
    const int tx  = tid & 15;
    const int ty  = tid >> 4;
    const int m0  = blockIdx.x * 128;
    const int n0  = blockIdx.y * 128;

    const int arow = tid >> 1;
    const int akg  = (tid & 1) * 4;
    const int brow = tid >> 5;
    const int bc   = (tid & 31) * 4;

    const float* ap = x + (size_t)(m0 + arow) * 256 + akg;
    const float* bp = w + (size_t)brow * 768 + n0 + bc;

    float acc[8][8];
    #pragma unroll
    for (int u = 0; u < 8; u++)
        #pragma unroll
        for (int v = 0; v < 8; v++) acc[u][v] = 0.f;

    {
        float4 av = *(const float4*)(ap);
        float4 bv = *(const float4*)(bp);
        QKV_STORE(0, av, bv);
    }
    __syncthreads();

    for (int k0 = 0; k0 < 256; k0 += 16) {
        {
            float4 av = *(const float4*)(ap + k0 + 8);
            float4 bv = *(const float4*)(bp + (size_t)(k0 + 8) * 768);
            QKV_COMPUTE(0);
            QKV_STORE(1, av, bv);
            __syncthreads();
        }
        {
            const bool hn = (k0 + 16) < 256;
            float4 av, bv;
            if (hn) {
                av = *(const float4*)(ap + k0 + 16);
                bv = *(const float4*)(bp + (size_t)(k0 + 16) * 768);
            }
            QKV_COMPUTE(1);
            if (hn) {
                QKV_STORE(0, av, bv);
                __syncthreads();
            }
        }
    }

    #pragma unroll
    for (int u = 0; u < 8; u++) {
        const int r  = m0 + ty * 8 + u;
        const int bw = r / NTOK;
        const int i  = r - bw * NTOK;
        #pragma unroll
        for (int v0 = 0; v0 < 8; v0 += 4) {
            const int c    = n0 + tx * 8 + v0;
            const int part = c >> 8;
            const int cc   = c & 255;
            const int h    = cc >> 5;
            const int d    = cc & 31;
            float4 vv;
            vv.x = acc[u][v0 + 0] + bias[c + 0];
            vv.y = acc[u][v0 + 1] + bias[c + 1];
            vv.z = acc[u][v0 + 2] + bias[c + 2];
            vv.w = acc[u][v0 + 3] + bias[c + 3];
            float* dst;
            if (part == 0) {
                vv.x *= QSCALE; vv.y *= QSCALE; vv.z *= QSCALE; vv.w *= QSCALE;
                dst = g_q;
            } else {
                dst = (part == 1) ? g_k : g_v;
            }
            *(float4*)&dst[(size_t)((bw * NHEAD + h) * NTOK + i) * HD + d] = vv;
        }
    }
}

// =================================================================================
// Kernel 2: fused attention, 4-row register blocking per warp + f32x2 QK.
// One block = one (bw, head). 256 threads (8 warps), 1 block/SM.
// smem: K(343x36), V(352x36 zero-padded), p-buffers (8 warps x 4 rows x 352).
// =================================================================================
__global__ __launch_bounds__(256) void attn_kernel(
    const float* __restrict__ mask)
{
    extern __shared__ float sm[];
    float* Ks = sm;                       // 343*36
    float* Vs = Ks + NTOK * 36;           // 352*36
    float* ps = Vs + PSTR * 36;           // 8*4*352

    const int bx  = blockIdx.x;
    const int bw  = bx >> 3;
    const int h   = bx & 7;
    const int tid = threadIdx.x;

    const float* kb = g_k + (size_t)(bw * NHEAD + h) * NTOK * HD;
    const float* vb = g_v + (size_t)(bw * NHEAD + h) * NTOK * HD;

    // ---- cooperative load of K, V (V zero-padded to 352 rows) ----
    for (int idx = tid; idx < PSTR * 8; idx += 256) {
        const int row = idx >> 3;
        const int c4  = idx & 7;
        if (row < NTOK) {
            *(float4*)&Ks[row * 36 + c4 * 4] = ((const float4*)kb)[idx];
            *(float4*)&Vs[row * 36 + c4 * 4] = ((const float4*)vb)[idx];
        } else {
            *(float4*)&Vs[row * 36 + c4 * 4] = make_float4(0.f, 0.f, 0.f, 0.f);
        }
    }
    // zero p-buffers (pad columns j>=343 must stay 0 for vectorized PV)
    for (int idx = tid; idx < 8 * 4 * PSTR; idx += 256) ps[idx] = 0.f;
    __syncthreads();

    const int warp = tid >> 5;
    const int lane = tid & 31;
    const int g    = lane >> 3;   // j-group / output row select
    const int dq   = lane & 7;    // float4 index into head dim

    const float* qb   = g_q + (size_t)(bw * NHEAD + h) * NTOK * HD;
    const float* mrow = mask + (size_t)(bw & (NWND - 1)) * NN;
    const float* brow = g_bias + (size_t)h * NN;
    float*       po   = g_o + (size_t)bw * NTOK * CDIM + h * HD;
    float*       psw  = ps + warp * 4 * PSTR;

    for (int ib = warp; ib < (NTOK + 3) / 4; ib += 8) {
        const int i0 = 4 * ib;
        int ir0 = i0,     ir1 = min(i0 + 1, NTOK - 1);
        int ir2 = min(i0 + 2, NTOK - 1), ir3 = min(i0 + 3, NTOK - 1);

        // ---- q rows into registers as packed f32x2 pairs (natural layout) ----
        ulonglong2 qv0[8], qv1[8], qv2[8], qv3[8];
        {
            const ulonglong2* qp0 = (const ulonglong2*)(qb + ir0 * HD);
            const ulonglong2* qp1 = (const ulonglong2*)(qb + ir1 * HD);
            const ulonglong2* qp2 = (const ulonglong2*)(qb + ir2 * HD);
            const ulonglong2* qp3 = (const ulonglong2*)(qb + ir3 * HD);
            #pragma unroll
            for (int u = 0; u < 8; u++) {
                qv0[u] = qp0[u]; qv1[u] = qp1[u];
                qv2[u] = qp2[u]; qv3[u] = qp3[u];
            }
        }

        const float* bi0 = brow + (size_t)ir0 * NTOK;
        const float* bi1 = brow + (size_t)ir1 * NTOK;
        const float* bi2 = brow + (size_t)ir2 * NTOK;
        const float* bi3 = brow + (size_t)ir3 * NTOK;
        const float* mi0 = mrow + (size_t)ir0 * NTOK;
        const float* mi1 = mrow + (size_t)ir1 * NTOK;
        const float* mi2 = mrow + (size_t)ir2 * NTOK;
        const float* mi3 = mrow + (size_t)ir3 * NTOK;

        // ---- pass 1: scores (f32x2 dot products), pipelined bias/mask loads ----
        float mx0 = -1e30f, mx1 = -1e30f, mx2 = -1e30f, mx3 = -1e30f;
        float bp0, bp1, bp2, bp3, mp0, mp1, mp2, mp3;
        {
            const int j = lane;   // always < 343
            bp0 = __ldg(bi0 + j); bp1 = __ldg(bi1 + j);
            bp2 = __ldg(bi2 + j); bp3 = __ldg(bi3 + j);
            mp0 = __ldg(mi0 + j); mp1 = __ldg(mi1 + j);
            mp2 = __ldg(mi2 + j); mp3 = __ldg(mi3 + j);
        }
        for (int t = 0; t < 11; t++) {
            const int j = lane + 32 * t;
            const float bc0 = bp0, bc1 = bp1, bc2 = bp2, bc3 = bp3;
            const float mc0 = mp0, mc1 = mp1, mc2 = mp2, mc3 = mp3;
            const int jn = j + 32;
            if (jn < NTOK) {   // prefetch next t's bias/mask
                bp0 = __ldg(bi0 + jn); bp1 = __ldg(bi1 + jn);
                bp2 = __ldg(bi2 + jn); bp3 = __ldg(bi3 + jn);
                mp0 = __ldg(mi0 + jn); mp1 = __ldg(mi1 + jn);
                mp2 = __ldg(mi2 + jn); mp3 = __ldg(mi3 + jn);
            }
            if (j < NTOK) {
                unsigned long long a01_0 = 0, a23_0 = 0, a01_1 = 0, a23_1 = 0;
                unsigned long long a01_2 = 0, a23_2 = 0, a01_3 = 0, a23_3 = 0;
                const float* kr = &Ks[j * 36];
                #pragma unroll
                for (int dc = 0; dc < 8; dc++) {
                    ulonglong2 kv = *(const ulonglong2*)(kr + dc * 4);
                    fma2(a01_0, qv0[dc].x, kv.x); fma2(a23_0, qv0[dc].y, kv.y);
                    fma2(a01_1, qv1[dc].x, kv.x); fma2(a23_1, qv1[dc].y, kv.y);
                    fma2(a01_2, qv2[dc].x, kv.x); fma2(a23_2, qv2[dc].y, kv.y);
                    fma2(a01_3, qv3[dc].x, kv.x); fma2(a23_3, qv3[dc].y, kv.y);
                }
                float2 fA, fB;
                fA = unpack2(a01_0); fB = unpack2(a23_0);
                float s0 = (fA.x + fA.y) + (fB.x + fB.y) + bc0 + mc0;
                fA = unpack2(a01_1); fB = unpack2(a23_1);
                float s1 = (fA.x + fA.y) + (fB.x + fB.y) + bc1 + mc1;
                fA = unpack2(a01_2); fB = unpack2(a23_2);
                float s2 = (fA.x + fA.y) + (fB.x + fB.y) + bc2 + mc2;
                fA = unpack2(a01_3); fB = unpack2(a23_3);
                float s3 = (fA.x + fA.y) + (fB.x + fB.y) + bc3 + mc3;
                psw[0 * PSTR + j] = s0;  mx0 = fmaxf(mx0, s0);
                psw[1 * PSTR + j] = s1;  mx1 = fmaxf(mx1, s1);
                psw[2 * PSTR + j] = s2;  mx2 = fmaxf(mx2, s2);
                psw[3 * PSTR + j] = s3;  mx3 = fmaxf(mx3, s3);
            }
        }
        #pragma unroll
        for (int off = 16; off; off >>= 1) {
            mx0 = fmaxf(mx0, __shfl_xor_sync(0xFFFFFFFFu, mx0, off));
            mx1 = fmaxf(mx1, __shfl_xor_sync(0xFFFFFFFFu, mx1, off));
            mx2 = fmaxf(mx2, __shfl_xor_sync(0xFFFFFFFFu, mx2, off));
            mx3 = fmaxf(mx3, __shfl_xor_sync(0xFFFFFFFFu, mx3, off));
        }

        // ---- pass 2: exp + row sums (each lane touches only its own j's) ----
        float su0 = 0.f, su1 = 0.f, su2 = 0.f, su3 = 0.f;
        for (int t = 0; t < 11; t++) {
            const int j = lane + 32 * t;
            if (j < NTOK) {
                float p0 = exp2f((psw[0 * PSTR + j] - mx0) * LOG2E);
                float p1 = exp2f((psw[1 * PSTR + j] - mx1) * LOG2E);
                float p2 = exp2f((psw[2 * PSTR + j] - mx2) * LOG2E);
                float p3 = exp2f((psw[3 * PSTR + j] - mx3) * LOG2E);
                psw[0 * PSTR + j] = p0;  su0 += p0;
                psw[1 * PSTR + j] = p1;  su1 += p1;
                psw[2 * PSTR + j] = p2;  su2 += p2;
                psw[3 * PSTR + j] = p3;  su3 += p3;
            }
        }
        #pragma unroll
        for (int off = 16; off; off >>= 1) {
            su0 += __shfl_xor_sync(0xFFFFFFFFu, su0, off);
            su1 += __shfl_xor_sync(0xFFFFFFFFu, su1, off);
            su2 += __shfl_xor_sync(0xFFFFFFFFu, su2, off);
            su3 += __shfl_xor_sync(0xFFFFFFFFu, su3, off);
        }
        const float ri0 = 1.f / su0, ri1 = 1.f / su1;
        const float ri2 = 1.f / su2, ri3 = 1.f / su3;
        __syncwarp();   // PV reads other lanes' p's

        // ---- PV: 4 rows per V read; 4 j-groups x 4 j per iteration ----
        float a00 = 0.f, a01 = 0.f, a02 = 0.f, a03 = 0.f;
        float a10 = 0.f, a11 = 0.f, a12 = 0.f, a13 = 0.f;
        float a20 = 0.f, a21 = 0.f, a22 = 0.f, a23 = 0.f;
        float a30 = 0.f, a31 = 0.f, a32 = 0.f, a33 = 0.f;
        #pragma unroll 2
        for (int jt = 0; jt < PSTR / 16; jt++) {       // 22 iterations
            const int j0 = jt * 16 + g * 4;
            float4 p0 = *(const float4*)&psw[0 * PSTR + j0];
            float4 p1 = *(const float4*)&psw[1 * PSTR + j0];
            float4 p2 = *(const float4*)&psw[2 * PSTR + j0];
            float4 p3 = *(const float4*)&psw[3 * PSTR + j0];
            float4 v0 = *(const float4*)&Vs[(j0 + 0) * 36 + dq * 4];
            float4 v1 = *(const float4*)&Vs[(j0 + 1) * 36 + dq * 4];
            float4 v2 = *(const float4*)&Vs[(j0 + 2) * 36 + dq * 4];
            float4 v3 = *(const float4*)&Vs[(j0 + 3) * 36 + dq * 4];
            a00 += p0.x * v0.x; a01 += p0.x * v0.y; a02 += p0.x * v0.z; a03 += p0.x * v0.w;
            a10 += p1.x * v0.x; a11 += p1.x * v0.y; a12 += p1.x * v0.z; a13 += p1.x * v0.w;
            a20 += p2.x * v0.x; a21 += p2.x * v0.y; a22 += p2.x * v0.z; a23 += p2.x * v0.w;
            a30 += p3.x * v0.x; a31 += p3.x * v0.y; a32 += p3.x * v0.z; a33 += p3.x * v0.w;
            a00 += p0.y * v1.x; a01 += p0.y * v1.y; a02 += p0.y * v1.z; a03 += p0.y * v1.w;
            a10 += p1.y * v1.x; a11 += p1.y * v1.y; a12 += p1.y * v1.z; a13 += p1.y * v1.w;
            a20 += p2.y * v1.x; a21 += p2.y * v1.y; a22 += p2.y * v1.z; a23 += p2.y * v1.w;
            a30 += p3.y * v1.x; a31 += p3.y * v1.y; a32 += p3.y * v1.z; a33 += p3.y * v1.w;
            a00 += p0.z * v2.x; a01 += p0.z * v2.y; a02 += p0.z * v2.z; a03 += p0.z * v2.w;
            a10 += p1.z * v2.x; a11 += p1.z * v2.y; a12 += p1.z * v2.z; a13 += p1.z * v2.w;
            a20 += p2.z * v2.x; a21 += p2.z * v2.y; a22 += p2.z * v2.z; a23 += p2.z * v2.w;
            a30 += p3.z * v2.x; a31 += p3.z * v2.y; a32 += p3.z * v2.z; a33 += p3.z * v2.w;
            a00 += p0.w * v3.x; a01 += p0.w * v3.y; a02 += p0.w * v3.z; a03 += p0.w * v3.w;
            a10 += p1.w * v3.x; a11 += p1.w * v3.y; a12 += p1.w * v3.z; a13 += p1.w * v3.w;
            a20 += p2.w * v3.x; a21 += p2.w * v3.y; a22 += p2.w * v3.z; a23 += p2.w * v3.w;
            a30 += p3.w * v3.x; a31 += p3.w * v3.y; a32 += p3.w * v3.z; a33 += p3.w * v3.w;
        }
        // combine the 4 j-groups; afterwards every lane holds all rows' sums
        #pragma unroll
        for (int off = 8; off <= 16; off <<= 1) {
            a00 += __shfl_xor_sync(0xFFFFFFFFu, a00, off);
            a01 += __shfl_xor_sync(0xFFFFFFFFu, a01, off);
            a02 += __shfl_xor_sync(0xFFFFFFFFu, a02, off);
            a03 += __shfl_xor_sync(0xFFFFFFFFu, a03, off);
            a10 += __shfl_xor_sync(0xFFFFFFFFu, a10, off);
            a11 += __shfl_xor_sync(0xFFFFFFFFu, a11, off);
            a12 += __shfl_xor_sync(0xFFFFFFFFu, a12, off);
            a13 += __shfl_xor_sync(0xFFFFFFFFu, a13, off);
            a20 += __shfl_xor_sync(0xFFFFFFFFu, a20, off);
            a21 += __shfl_xor_sync(0xFFFFFFFFu, a21, off);
            a22 += __shfl_xor_sync(0xFFFFFFFFu, a22, off);
            a23 += __shfl_xor_sync(0xFFFFFFFFu, a23, off);
            a30 += __shfl_xor_sync(0xFFFFFFFFu, a30, off);
            a31 += __shfl_xor_sync(0xFFFFFFFFu, a31, off);
            a32 += __shfl_xor_sync(0xFFFFFFFFu, a32, off);
            a33 += __shfl_xor_sync(0xFFFFFFFFu, a33, off);
        }

        // lane-group g writes row i0+g, head-dim chunk dq
        {
            const float rr =
                (g == 0) ? ri0 : ((g == 1) ? ri1 : ((g == 2) ? ri2 : ri3));
            const float o0 =
                (g == 0) ? a00 : ((g == 1) ? a10 : ((g == 2) ? a20 : a30));
            const float o1 =
                (g == 0) ? a01 : ((g == 1) ? a11 : ((g == 2) ? a21 : a31));
            const float o2 =
                (g == 0) ? a02 : ((g == 1) ? a12 : ((g == 2) ? a22 : a32));
            const float o3 =
                (g == 0) ? a03 : ((g == 1) ? a13 : ((g == 2) ? a23 : a33));
            const int row = i0 + g;
            if (row < NTOK) {
                float4 ov = make_float4(o0 * rr, o1 * rr, o2 * rr, o3 * rr);
                *(float4*)&po[(size_t)row * CDIM + dq * 4] = ov;
            }
        }
        __syncwarp();   // protect psw before next group's pass-1 writes
    }
}

// =================================================================================
// Kernel 3: out = g_o @ proj_w + proj_b. A: (87808 x 256), B: (256 x 256).
// =================================================================================
__global__ __launch_bounds__(256) void proj_gemm_kernel(
    const float* __restrict__ w,
    const float* __restrict__ bias,
    float* __restrict__ out)
{
    __shared__ float As[2][8][132];
    __shared__ float Bs[2][8][132];

    const int tid = threadIdx.x;
    const int tx  = tid & 15;
    const int ty  = tid >> 4;
    const int m0  = blockIdx.x * 128;
    const int n0  = blockIdx.y * 128;

    const int arow = tid >> 1;
    const int akg  = (tid & 1) * 4;
    const int brow = tid >> 5;
    const int bc   = (tid & 31) * 4;

    const float* ap = g_o + (size_t)(m0 + arow) * 256 + akg;
    const float* bp = w + (size_t)brow * 256 + n0 + bc;

    float acc[8][8];
    #pragma unroll
    for (int u = 0; u < 8; u++)
        #pragma unroll
        for (int v = 0; v < 8; v++) acc[u][v] = 0.f;

    {
        float4 av = *(const float4*)(ap);
        float4 bv = *(const float4*)(bp);
        QKV_STORE(0, av, bv);
    }
    __syncthreads();

    for (int k0 = 0; k0 < 256; k0 += 16) {
        {
            float4 av = *(const float4*)(ap + k0 + 8);
            float4 bv = *(const float4*)(bp + (size_t)(k0 + 8) * 256);
            QKV_COMPUTE(0);
            QKV_STORE(1, av, bv);
            __syncthreads();
        }
        {
            const bool hn = (k0 + 16) < 256;
            float4 av, bv;
            if (hn) {
                av = *(const float4*)(ap + k0 + 16);
                bv = *(const float4*)(bp + (size_t)(k0 + 16) * 256);
            }
            QKV_COMPUTE(1);
            if (hn) {
                QKV_STORE(0, av, bv);
                __syncthreads();
            }
        }
    }

    #pragma unroll
    for (int u = 0; u < 8; u++) {
        const int r = m0 + ty * 8 + u;
        #pragma unroll
        for (int v0 = 0; v0 < 8; v0 += 4) {
            const int c = n0 + tx * 8 + v0;
            float4 vv;
            vv.x = acc[u][v0 + 0] + bias[c + 0];
            vv.y = acc[u][v0 + 1] + bias[c + 1];
            vv.z = acc[u][v0 + 2] + bias[c + 2];
            vv.w = acc[u][v0 + 3] + bias[c + 3];
            *(float4*)&out[(size_t)r * 256 + c] = vv;
        }
    }
}

// =================================================================================
extern "C" void kernel_launch(void* const* d_in, const int* in_sizes, int n_in,
                              void* d_out, int out_size)
{
    const float* x       = (const float*)d_in[0];
    const float* mask    = (const float*)d_in[1];
    const float* qkv_w   = (const float*)d_in[2];
    const float* qkv_b   = (const float*)d_in[3];
    const float* proj_w  = (const float*)d_in[4];
    const float* proj_b  = (const float*)d_in[5];
    const float* rpb     = (const float*)d_in[6];
    const int*   rel_idx = (const int*)d_in[7];
    float* out = (float*)d_out;

    // 0) bias gather
    bias_gather_kernel<<<(NN + 255) / 256, 256>>>(rpb, rel_idx);

    // 1) QKV projection + scatter
    qkv_gemm_kernel<<<dim3(686, 6), 256>>>(x, qkv_w, qkv_b);

    // 2) fused window attention (4-row blocked, f32x2 QK)
    const size_t smem_bytes =
        (size_t)(NTOK * 36 + PSTR * 36 + 8 * 4 * PSTR) * sizeof(float);  // ~141.7 KB
    cudaFuncSetAttribute(attn_kernel,
                         cudaFuncAttributeMaxDynamicSharedMemorySize,
                         (int)smem_bytes);
    attn_kernel<<<BWIN * NHEAD, 256, smem_bytes>>>(mask);

    // 3) output projection
    proj_gemm_kernel<<<dim3(686, 2), 256>>>(proj_w, proj_b, out);
}

// round 17
// speedup vs baseline: 1.0765x; 1.0765x over previous
#include <cuda_runtime.h>
#include <cstdint>

#define NTOK  343
#define NPAD  352          // padded j-extent for PV (16-divisible)
#define NHEAD 8
#define CDIM  256
#define HD    32
#define BWIN  256
#define NWND  64
#define NN    (NTOK * NTOK)   // 117649
#define QSCALE 0.17677669529663687f   // 32^-0.5
#define LOG2E  1.4426950408889634f

// ---------------- scratch (device globals: no allocation allowed) ----------------
__device__ float g_q[(size_t)BWIN * NHEAD * NTOK * HD];   // scaled q, (Bw,H,n,hd)
__device__ float g_k[(size_t)BWIN * NHEAD * NTOK * HD];
__device__ float g_v[(size_t)BWIN * NHEAD * NTOK * HD];
__device__ float g_o[(size_t)BWIN * NTOK * CDIM];         // attention out, (Bw,n,C)
__device__ float g_bias[(size_t)NHEAD * NN];              // gathered rpb bias (H,n,n)

// ---------------- packed fp32x2 helpers ----------------
__device__ __forceinline__ void fma2(unsigned long long& acc,
                                     const unsigned long long a,
                                     const unsigned long long b) {
    asm("fma.rn.f32x2 %0, %1, %2, %0;" : "+l"(acc) : "l"(a), "l"(b));
}
__device__ __forceinline__ float2 unpack2(const unsigned long long x) {
    float2 r;
    asm("mov.b64 {%0, %1}, %2;" : "=f"(r.x), "=f"(r.y) : "l"(x));
    return r;
}

// =================================================================================
// Kernel 0: gather relative-position bias: g_bias[h][p] = rpb[rel_idx[p]*8 + h]
// =================================================================================
__global__ __launch_bounds__(256) void bias_gather_kernel(
    const float* __restrict__ rpb,
    const int*   __restrict__ rel_idx)
{
    const int p = blockIdx.x * 256 + threadIdx.x;
    if (p >= NN) return;
    const int idx = rel_idx[p];
    float4 r0 = *(const float4*)(rpb + (size_t)idx * 8);
    float4 r1 = *(const float4*)(rpb + (size_t)idx * 8 + 4);
    g_bias[0 * (size_t)NN + p] = r0.x;
    g_bias[1 * (size_t)NN + p] = r0.y;
    g_bias[2 * (size_t)NN + p] = r0.z;
    g_bias[3 * (size_t)NN + p] = r0.w;
    g_bias[4 * (size_t)NN + p] = r1.x;
    g_bias[5 * (size_t)NN + p] = r1.y;
    g_bias[6 * (size_t)NN + p] = r1.z;
    g_bias[7 * (size_t)NN + p] = r1.w;
}

// =================================================================================
// Shared GEMM macros (BM=128, BN=128, BK=8 double-buffered, 256 threads, 8x8)
// =================================================================================
#define QKV_STAGE(BUF, KK)                                                  \
    {                                                                       \
        float a[8], b[8];                                                   \
        *(float4*)(a)     = *(const float4*)&As[BUF][KK][ty * 8];           \
        *(float4*)(a + 4) = *(const float4*)&As[BUF][KK][ty * 8 + 4];       \
        *(float4*)(b)     = *(const float4*)&Bs[BUF][KK][tx * 8];           \
        *(float4*)(b + 4) = *(const float4*)&Bs[BUF][KK][tx * 8 + 4];       \
        _Pragma("unroll")                                                   \
        for (int u = 0; u < 8; u++)                                         \
            _Pragma("unroll")                                               \
            for (int v = 0; v < 8; v++) acc[u][v] += a[u] * b[v];           \
    }
#define QKV_COMPUTE(BUF)                                                    \
    { _Pragma("unroll") for (int kk = 0; kk < 8; kk++) QKV_STAGE(BUF, kk) }
#define QKV_STORE(BUF, AV, BV)                                              \
    {                                                                       \
        As[BUF][akg + 0][arow] = (AV).x;                                    \
        As[BUF][akg + 1][arow] = (AV).y;                                    \
        As[BUF][akg + 2][arow] = (AV).z;                                    \
        As[BUF][akg + 3][arow] = (AV).w;                                    \
        *(float4*)&Bs[BUF][brow][bc] = (BV);                                \
    }

// =================================================================================
// Kernel 1: QKV = x @ qkv_w + qkv_b, scatter to g_q (scaled), g_k, g_v
// =================================================================================
__global__ __launch_bounds__(256) void qkv_gemm_kernel(
    const float* __restrict__ x,
    const float* __restrict__ w,
    const float* __restrict__ bias)
{
    __shared__ float As[2][8][132];
    __shared__ float Bs[2][8][132];

    const int tid = threadIdx.x;
    const int tx  = tid & 15;
    const int ty  = tid >> 4;
    const int m0  = blockIdx.x * 128;
    const int n0  = blockIdx.y * 128;

    const int arow = tid >> 1;
    const int akg  = (tid & 1) * 4;
    const int brow = tid >> 5;
    const int bc   = (tid & 31) * 4;

    const float* ap = x + (size_t)(m0 + arow) * 256 + akg;
    const float* bp = w + (size_t)brow * 768 + n0 + bc;

    float acc[8][8];
    #pragma unroll
    for (int u = 0; u < 8; u++)
        #pragma unroll
        for (int v = 0; v < 8; v++) acc[u][v] = 0.f;

    {
        float4 av = *(const float4*)(ap);
        float4 bv = *(const float4*)(bp);
        QKV_STORE(0, av, bv);
    }
    __syncthreads();

    for (int k0 = 0; k0 < 256; k0 += 16) {
        {
            float4 av = *(const float4*)(ap + k0 + 8);
            float4 bv = *(const float4*)(bp + (size_t)(k0 + 8) * 768);
            QKV_COMPUTE(0);
            QKV_STORE(1, av, bv);
            __syncthreads();
        }
        {
            const bool hn = (k0 + 16) < 256;
            float4 av, bv;
            if (hn) {
                av = *(const float4*)(ap + k0 + 16);
                bv = *(const float4*)(bp + (size_t)(k0 + 16) * 768);
            }
            QKV_COMPUTE(1);
            if (hn) {
                QKV_STORE(0, av, bv);
                __syncthreads();
            }
        }
    }

    #pragma unroll
    for (int u = 0; u < 8; u++) {
        const int r  = m0 + ty * 8 + u;
        const int bw = r / NTOK;
        const int i  = r - bw * NTOK;
        #pragma unroll
        for (int v0 = 0; v0 < 8; v0 += 4) {
            const int c    = n0 + tx * 8 + v0;
            const int part = c >> 8;
            const int cc   = c & 255;
            const int h    = cc >> 5;
            const int d    = cc & 31;
            float4 vv;
            vv.x = acc[u][v0 + 0] + bias[c + 0];
            vv.y = acc[u][v0 + 1] + bias[c + 1];
            vv.z = acc[u][v0 + 2] + bias[c + 2];
            vv.w = acc[u][v0 + 3] + bias[c + 3];
            float* dst;
            if (part == 0) {
                vv.x *= QSCALE; vv.y *= QSCALE; vv.z *= QSCALE; vv.w *= QSCALE;
                dst = g_q;
            } else {
                dst = (part == 1) ? g_k : g_v;
            }
            *(float4*)&dst[(size_t)((bw * NHEAD + h) * NTOK + i) * HD + d] = vv;
        }
    }
}

// =================================================================================
// Kernel 2: fused attention, 2-row register blocking per warp, f32x2 QK,
// vectorized PV. One block = one (bw, head). 512 threads (16 warps).
// smem: K(343x36), V(352x36 zero-padded), p-buffers (16 x 2 x 352 zero-padded).
// =================================================================================
__global__ __launch_bounds__(512) void attn_kernel(
    const float* __restrict__ mask)
{
    extern __shared__ float sm[];
    float* Ks  = sm;                      // 343*36
    float* Vs  = Ks + NTOK * 36;          // 352*36
    float* ps  = Vs + NPAD * 36;          // 16*2*352

    const int bx = blockIdx.x;
    const int bw = bx >> 3;
    const int h  = bx & 7;
    const int tid = threadIdx.x;

    const float* kb = g_k + (size_t)(bw * NHEAD + h) * NTOK * HD;
    const float* vb = g_v + (size_t)(bw * NHEAD + h) * NTOK * HD;

    // ---- cooperative load of K, V (padded); zero V pad rows and all p-buffers ----
    for (int idx = tid; idx < NPAD * 8; idx += 512) {
        const int row = idx >> 3;
        const int c4  = idx & 7;
        if (row < NTOK) {
            float4 kv = ((const float4*)kb)[idx];
            *(float4*)&Ks[row * 36 + c4 * 4] = kv;
            float4 vv = ((const float4*)vb)[idx];
            *(float4*)&Vs[row * 36 + c4 * 4] = vv;
        } else {
            *(float4*)&Vs[row * 36 + c4 * 4] = make_float4(0.f, 0.f, 0.f, 0.f);
        }
    }
    for (int idx = tid; idx < 16 * 2 * NPAD; idx += 512) ps[idx] = 0.f;
    __syncthreads();

    const int warp = tid >> 5;
    const int lane = tid & 31;
    const int g    = lane >> 3;   // j-group (0..3)
    const int dq   = lane & 7;    // float4 index into head dim

    const float* qb   = g_q + (size_t)(bw * NHEAD + h) * NTOK * HD;
    const float* mrow = mask + (size_t)(bw & (NWND - 1)) * NN;
    const float* brow = g_bias + (size_t)h * NN;
    float*       po   = g_o + (size_t)bw * NTOK * CDIM + h * HD;
    float*       ps0  = ps + warp * 2 * NPAD;
    float*       ps1  = ps0 + NPAD;

    for (int ib = warp; ib < (NTOK + 1) / 2; ib += 16) {
        const int i0  = 2 * ib;
        const int i1r = 2 * ib + 1;
        const bool valid1 = (i1r < NTOK);
        const int i1 = valid1 ? i1r : (NTOK - 1);

        // q rows into registers as packed f32x2 pairs (layout-identical to float4)
        ulonglong2 q0[8], q1[8];
        {
            const ulonglong2* qp0 = (const ulonglong2*)(qb + i0 * HD);
            const ulonglong2* qp1 = (const ulonglong2*)(qb + i1 * HD);
            #pragma unroll
            for (int u = 0; u < 8; u++) { q0[u] = qp0[u]; q1[u] = qp1[u]; }
        }

        const float* bi0 = brow + (size_t)i0 * NTOK;
        const float* bi1 = brow + (size_t)i1 * NTOK;
        const float* mi0 = mrow + (size_t)i0 * NTOK;
        const float* mi1 = mrow + (size_t)i1 * NTOK;

        // ---- pass 1: scores into smem (f32x2 dot products), track per-lane max ----
        float mx0 = -1e30f, mx1 = -1e30f;
        #pragma unroll
        for (int t = 0; t < 11; t++) {
            const int j = lane + 32 * t;
            if (j < NTOK) {
                const float* kr = &Ks[j * 36];
                unsigned long long aA0 = 0, aB0 = 0;   // row 0: pairs (4 lanes of f32x2)
                unsigned long long aA1 = 0, aB1 = 0;   // row 1
                #pragma unroll
                for (int u = 0; u < 8; u++) {
                    ulonglong2 kv = *(const ulonglong2*)(kr + u * 4);
                    fma2(aA0, q0[u].x, kv.x);  fma2(aB0, q0[u].y, kv.y);
                    fma2(aA1, q1[u].x, kv.x);  fma2(aB1, q1[u].y, kv.y);
                }
                float2 fA = unpack2(aA0), fB = unpack2(aB0);
                float sc0 = (fA.x + fA.y) + (fB.x + fB.y);
                fA = unpack2(aA1); fB = unpack2(aB1);
                float sc1 = (fA.x + fA.y) + (fB.x + fB.y);
                sc0 += __ldg(bi0 + j) + __ldg(mi0 + j);
                sc1 += __ldg(bi1 + j) + __ldg(mi1 + j);
                ps0[j] = sc0;
                ps1[j] = sc1;
                mx0 = fmaxf(mx0, sc0);
                mx1 = fmaxf(mx1, sc1);
            }
        }
        #pragma unroll
        for (int off = 16; off; off >>= 1) {
            mx0 = fmaxf(mx0, __shfl_xor_sync(0xFFFFFFFFu, mx0, off));
            mx1 = fmaxf(mx1, __shfl_xor_sync(0xFFFFFFFFu, mx1, off));
        }
        __syncwarp();

        // ---- pass 2: scores -> probabilities, accumulate sums ----
        float sum0 = 0.f, sum1 = 0.f;
        #pragma unroll
        for (int t = 0; t < 11; t++) {
            const int j = lane + 32 * t;
            if (j < NTOK) {
                float p0 = exp2f((ps0[j] - mx0) * LOG2E);
                float p1 = exp2f((ps1[j] - mx1) * LOG2E);
                ps0[j] = p0;
                ps1[j] = p1;
                sum0 += p0;
                sum1 += p1;
            }
        }
        #pragma unroll
        for (int off = 16; off; off >>= 1) {
            sum0 += __shfl_xor_sync(0xFFFFFFFFu, sum0, off);
            sum1 += __shfl_xor_sync(0xFFFFFFFFu, sum1, off);
        }
        const float rinv0 = 1.f / sum0;
        const float rinv1 = 1.f / sum1;
        __syncwarp();

        // ---- PV: 4 lane-groups x 4 consecutive j per iteration (vectorized p) ----
        float a0x = 0.f, a0y = 0.f, a0z = 0.f, a0w = 0.f;
        float a1x = 0.f, a1y = 0.f, a1z = 0.f, a1w = 0.f;
        #pragma unroll 2
        for (int jt = 0; jt < NPAD / 16; jt++) {       // 22 iterations
            const int j0 = jt * 16 + g * 4;
            float4 p0 = *(const float4*)&ps0[j0];
            float4 p1 = *(const float4*)&ps1[j0];
            float4 v0 = *(const float4*)&Vs[(j0 + 0) * 36 + dq * 4];
            float4 v1 = *(const float4*)&Vs[(j0 + 1) * 36 + dq * 4];
            float4 v2 = *(const float4*)&Vs[(j0 + 2) * 36 + dq * 4];
            float4 v3 = *(const float4*)&Vs[(j0 + 3) * 36 + dq * 4];
            a0x += p0.x * v0.x; a0y += p0.x * v0.y; a0z += p0.x * v0.z; a0w += p0.x * v0.w;
            a1x += p1.x * v0.x; a1y += p1.x * v0.y; a1z += p1.x * v0.z; a1w += p1.x * v0.w;
            a0x += p0.y * v1.x; a0y += p0.y * v1.y; a0z += p0.y * v1.z; a0w += p0.y * v1.w;
            a1x += p1.y * v1.x; a1y += p1.y * v1.y; a1z += p1.y * v1.z; a1w += p1.y * v1.w;
            a0x += p0.z * v2.x; a0y += p0.z * v2.y; a0z += p0.z * v2.z; a0w += p0.z * v2.w;
            a1x += p1.z * v2.x; a1y += p1.z * v2.y; a1z += p1.z * v2.z; a1w += p1.z * v2.w;
            a0x += p0.w * v3.x; a0y += p0.w * v3.y; a0z += p0.w * v3.z; a0w += p0.w * v3.w;
            a1x += p1.w * v3.x; a1y += p1.w * v3.y; a1z += p1.w * v3.z; a1w += p1.w * v3.w;
        }
        // combine the 4 j-groups (after this every lane has the full sums)
        #pragma unroll
        for (int off = 8; off <= 16; off <<= 1) {
            a0x += __shfl_xor_sync(0xFFFFFFFFu, a0x, off);
            a0y += __shfl_xor_sync(0xFFFFFFFFu, a0y, off);
            a0z += __shfl_xor_sync(0xFFFFFFFFu, a0z, off);
            a0w += __shfl_xor_sync(0xFFFFFFFFu, a0w, off);
            a1x += __shfl_xor_sync(0xFFFFFFFFu, a1x, off);
            a1y += __shfl_xor_sync(0xFFFFFFFFu, a1y, off);
            a1z += __shfl_xor_sync(0xFFFFFFFFu, a1z, off);
            a1w += __shfl_xor_sync(0xFFFFFFFFu, a1w, off);
        }

        if (lane < 8) {          // write row 0 (lane == dq)
            float4 ov = make_float4(a0x * rinv0, a0y * rinv0, a0z * rinv0, a0w * rinv0);
            *(float4*)&po[(size_t)i0 * CDIM + dq * 4] = ov;
        } else if (lane < 16 && valid1) {   // write row 1 (dq = lane-8)
            float4 ov = make_float4(a1x * rinv1, a1y * rinv1, a1z * rinv1, a1w * rinv1);
            *(float4*)&po[(size_t)i1r * CDIM + dq * 4] = ov;
        }
        __syncwarp();   // protect ps0/ps1 before next pair's writes
    }
}

// =================================================================================
// Kernel 3: out = g_o @ proj_w + proj_b. A: (87808 x 256), B: (256 x 256).
// =================================================================================
__global__ __launch_bounds__(256) void proj_gemm_kernel(
    const float* __restrict__ w,
    const float* __restrict__ bias,
    float* __restrict__ out)
{
    __shared__ float As[2][8][132];
    __shared__ float Bs[2][8][132];

    const int tid = threadIdx.x;
    const int tx  = tid & 15;
    const int ty  = tid >> 4;
    const int m0  = blockIdx.x * 128;
    const int n0  = blockIdx.y * 128;

    const int arow = tid >> 1;
    const int akg  = (tid & 1) * 4;
    const int brow = tid >> 5;
    const int bc   = (tid & 31) * 4;

    const float* ap = g_o + (size_t)(m0 + arow) * 256 + akg;
    const float* bp = w + (size_t)brow * 256 + n0 + bc;

    float acc[8][8];
    #pragma unroll
    for (int u = 0; u < 8; u++)
        #pragma unroll
        for (int v = 0; v < 8; v++) acc[u][v] = 0.f;

    {
        float4 av = *(const float4*)(ap);
        float4 bv = *(const float4*)(bp);
        QKV_STORE(0, av, bv);
    }
    __syncthreads();

    for (int k0 = 0; k0 < 256; k0 += 16) {
        {
            float4 av = *(const float4*)(ap + k0 + 8);
            float4 bv = *(const float4*)(bp + (size_t)(k0 + 8) * 256);
            QKV_COMPUTE(0);
            QKV_STORE(1, av, bv);
            __syncthreads();
        }
        {
            const bool hn = (k0 + 16) < 256;
            float4 av, bv;
            if (hn) {
                av = *(const float4*)(ap + k0 + 16);
                bv = *(const float4*)(bp + (size_t)(k0 + 16) * 256);
            }
            QKV_COMPUTE(1);
            if (hn) {
                QKV_STORE(0, av, bv);
                __syncthreads();
            }
        }
    }

    #pragma unroll
    for (int u = 0; u < 8; u++) {
        const int r = m0 + ty * 8 + u;
        #pragma unroll
        for (int v0 = 0; v0 < 8; v0 += 4) {
            const int c = n0 + tx * 8 + v0;
            float4 vv;
            vv.x = acc[u][v0 + 0] + bias[c + 0];
            vv.y = acc[u][v0 + 1] + bias[c + 1];
            vv.z = acc[u][v0 + 2] + bias[c + 2];
            vv.w = acc[u][v0 + 3] + bias[c + 3];
            *(float4*)&out[(size_t)r * 256 + c] = vv;
        }
    }
}

// =================================================================================
extern "C" void kernel_launch(void* const* d_in, const int* in_sizes, int n_in,
                              void* d_out, int out_size)
{
    const float* x       = (const float*)d_in[0];
    const float* mask    = (const float*)d_in[1];
    const float* qkv_w   = (const float*)d_in[2];
    const float* qkv_b   = (const float*)d_in[3];
    const float* proj_w  = (const float*)d_in[4];
    const float* proj_b  = (const float*)d_in[5];
    const float* rpb     = (const float*)d_in[6];
    const int*   rel_idx = (const int*)d_in[7];
    float* out = (float*)d_out;

    // 0) bias gather
    bias_gather_kernel<<<(NN + 255) / 256, 256>>>(rpb, rel_idx);

    // 1) QKV projection + scatter
    qkv_gemm_kernel<<<dim3(686, 6), 256>>>(x, qkv_w, qkv_b);

    // 2) fused window attention (2-row blocked, f32x2 QK, vectorized PV)
    const size_t smem_bytes =
        (size_t)(NTOK * 36 + NPAD * 36 + 16 * 2 * NPAD) * sizeof(float);  // ~142 KB
    cudaFuncSetAttribute(attn_kernel,
                         cudaFuncAttributeMaxDynamicSharedMemorySize,
                         (int)smem_bytes);
    attn_kernel<<<BWIN * NHEAD, 512, smem_bytes>>>(mask);

    // 3) output projection
    proj_gemm_kernel<<<dim3(686, 2), 256>>>(proj_w, proj_b, out);
}